// round 1
// baseline (speedup 1.0000x reference)
#include <cuda_runtime.h>
#include <math.h>

// ---------------- problem constants ----------------
#define C_N   1024
#define C_K   16
#define C_D   512
#define C_H   8
#define C_FF  2048
#define C_MA  64
#define C_ES  64
#define C_E   (C_N * C_K)      // 16384
#define C_EPS 1e-6f

// ---------------- scratch (device globals; no allocation) ----------------
__device__ float g_T   [3][C_N][C_D];        // tgt transposed (x-plane major)
__device__ float g_M   [3][C_E][C_D];        // memory transposed
__device__ float g_TV  [3][C_N][C_D];        // W_dst @ tgt
__device__ float g_MSG [3][C_E][C_D];        // W_src @ memory + tv
__device__ float g_w   [C_E][3*C_D];         // edge MLP output (w0|w1|w2)
__device__ float g_psc [C_E][C_D];           // scalar path
__device__ float g_PV  [3][C_E][C_D];        // p_v1 + p_v2
__device__ float g_araw[C_E][C_MA];          // p_sc @ W_alpha (pre-LN)
__device__ float g_attr[C_E][C_H];           // per-edge head logits
__device__ float g_att [C_E][C_H];           // softmaxed attention
__device__ float g_Z   [3][C_N][C_H][C_D];   // attention-weighted pv
__device__ float g_OUT [3][C_N][C_D];        // W_value applied to z
__device__ float g_XP  [3][C_N][C_D];        // tv + proj(out) (pre-norm)
__device__ float g_X1  [3][C_N][C_D];        // vn_ln #1 output
__device__ float g_Y   [3][C_N][C_FF];       // ff1 output
__device__ float g_DV  [3][C_N][C_FF];       // ffd output
__device__ float g_Y2  [3][C_N][C_FF];       // gated
__device__ float g_Y3  [3][C_N][C_D];        // x1 + ff2 (pre-norm)
__device__ float g_WaT [C_MA][C_D];          // W_alpha transposed

// ---------------- generic NT SGEMM: C[m,n] = sum_k A[m,k]*B[n,k] (+Add) ----------------
// All M / Nc / Kc used here are multiples of the tile dims (no bounds checks).
template<int TM, int TN, int TMI, int TNI>
__global__ void __launch_bounds__(256) gemm_nt(
    const float* __restrict__ A, const float* __restrict__ B,
    float* __restrict__ C, const float* __restrict__ Add,
    int M, int Nc, int Kc, int lda, int ldb, int ldc,
    long sA1, long sA2, long sB1, long sB2, long sC1, long sC2,
    int nz2, int addDiv, int ldadd, long sAdd1)
{
    __shared__ __align__(16) float As[16][TM + 4];
    __shared__ __align__(16) float Bs[16][TN + 4];

    const int z  = blockIdx.z;
    const int z1 = z / nz2, z2 = z - z1 * nz2;
    A += z1 * sA1 + z2 * sA2;
    B += z1 * sB1 + z2 * sB2;
    C += z1 * sC1 + z2 * sC2;
    if (Add) Add += z1 * sAdd1;

    const int m0 = blockIdx.y * TM, n0 = blockIdx.x * TN;
    const int t  = threadIdx.x;
    const int tx = t % (TN / TNI);
    const int ty = t / (TN / TNI);

    float acc[TMI][TNI];
#pragma unroll
    for (int i = 0; i < TMI; i++)
#pragma unroll
        for (int j = 0; j < TNI; j++) acc[i][j] = 0.f;

    for (int k0 = 0; k0 < Kc; k0 += 16) {
        for (int i = t; i < TM * 4; i += 256) {
            int r = i >> 2, c4 = (i & 3) << 2;
            float4 v = *reinterpret_cast<const float4*>(A + (long)(m0 + r) * lda + k0 + c4);
            As[c4 + 0][r] = v.x; As[c4 + 1][r] = v.y;
            As[c4 + 2][r] = v.z; As[c4 + 3][r] = v.w;
        }
        for (int i = t; i < TN * 4; i += 256) {
            int r = i >> 2, c4 = (i & 3) << 2;
            float4 v = *reinterpret_cast<const float4*>(B + (long)(n0 + r) * ldb + k0 + c4);
            Bs[c4 + 0][r] = v.x; Bs[c4 + 1][r] = v.y;
            Bs[c4 + 2][r] = v.z; Bs[c4 + 3][r] = v.w;
        }
        __syncthreads();
#pragma unroll
        for (int kk = 0; kk < 16; kk++) {
            float a[TMI], b[TNI];
#pragma unroll
            for (int i = 0; i < TMI; i += 4) {
                float4 v = *reinterpret_cast<const float4*>(&As[kk][ty * TMI + i]);
                a[i] = v.x; a[i + 1] = v.y; a[i + 2] = v.z; a[i + 3] = v.w;
            }
#pragma unroll
            for (int j = 0; j < TNI; j += 4) {
                float4 v = *reinterpret_cast<const float4*>(&Bs[kk][tx * TNI + j]);
                b[j] = v.x; b[j + 1] = v.y; b[j + 2] = v.z; b[j + 3] = v.w;
            }
#pragma unroll
            for (int i = 0; i < TMI; i++)
#pragma unroll
                for (int j = 0; j < TNI; j++)
                    acc[i][j] = fmaf(a[i], b[j], acc[i][j]);
        }
        __syncthreads();
    }

#pragma unroll
    for (int i = 0; i < TMI; i++) {
        int m = m0 + ty * TMI + i;
#pragma unroll
        for (int j = 0; j < TNI; j++) {
            int n = n0 + tx * TNI + j;
            float v = acc[i][j];
            if (Add) v += Add[(long)(m / addDiv) * ldadd + n];
            C[(long)m * ldc + n] = v;
        }
    }
}

// ---------------- transposes ----------------
__global__ void k_transpose_in(const float* __restrict__ tgt, const float* __restrict__ mem)
{
    long stride = (long)gridDim.x * blockDim.x;
    long base   = (long)blockIdx.x * blockDim.x + threadIdx.x;
    const long TT = (long)C_N * C_D * 3;
    for (long i = base; i < TT; i += stride) {
        int  x  = (int)(i % 3);
        long nc = i / 3;
        g_T[x][nc >> 9][nc & 511] = tgt[i];
    }
    const long TMm = (long)C_E * C_D * 3;
    for (long i = base; i < TMm; i += stride) {
        int  x  = (int)(i % 3);
        long ec = i / 3;
        g_M[x][ec >> 9][ec & 511] = mem[i];
    }
}

__global__ void k_transpose_wa(const float* __restrict__ wa)
{
    int i = blockIdx.x * blockDim.x + threadIdx.x;
    if (i < C_D * C_MA) g_WaT[i & 63][i >> 6] = wa[i];
}

// ---------------- fused edge MLP ----------------
__global__ void __launch_bounds__(256) k_mlp(
    const float* __restrict__ es, const float* __restrict__ w1, const float* __restrict__ b1,
    const float* __restrict__ w2, const float* __restrict__ b2,
    const float* __restrict__ w3, const float* __restrict__ b3)
{
    __shared__ float s_es[64][65];
    __shared__ float s_w1[64][32];
    __shared__ float s_w2[32][32];
    __shared__ float s_h1[64][33];
    __shared__ float s_h2[64][33];
    const int t = threadIdx.x;
    const long e0 = (long)blockIdx.x * 64;

    for (int i = t; i < 64 * 32; i += 256) s_w1[i >> 5][i & 31] = w1[i];
    for (int i = t; i < 32 * 32; i += 256) s_w2[i >> 5][i & 31] = w2[i];
    for (int i = t; i < 64 * 64; i += 256) s_es[i >> 6][i & 63] = es[e0 * 64 + i];
    __syncthreads();

    for (int i = t; i < 64 * 32; i += 256) {
        int e = i >> 5, j = i & 31;
        float acc = b1[j];
#pragma unroll 8
        for (int c = 0; c < 64; c++) acc = fmaf(s_es[e][c], s_w1[c][j], acc);
        s_h1[e][j] = acc / (1.f + expf(-acc));
    }
    __syncthreads();
    for (int i = t; i < 64 * 32; i += 256) {
        int e = i >> 5, j = i & 31;
        float acc = b2[j];
#pragma unroll 8
        for (int c = 0; c < 32; c++) acc = fmaf(s_h1[e][c], s_w2[c][j], acc);
        s_h2[e][j] = acc / (1.f + expf(-acc));
    }
    __syncthreads();
    for (int i = t; i < 64 * 1536; i += 256) {
        int e = i / 1536, o = i - e * 1536;
        float acc = b3[o];
#pragma unroll 8
        for (int c = 0; c < 32; c++) acc = fmaf(s_h2[e][c], w3[c * 1536 + o], acc);
        g_w[e0 + e][o] = acc;
    }
}

// ---------------- pointwise equivariant products ----------------
__global__ void k_pointwise(const float* __restrict__ esh)
{
    long stride = (long)gridDim.x * blockDim.x;
    for (long i = (long)blockIdx.x * blockDim.x + threadIdx.x; i < (long)C_E * C_D; i += stride) {
        int  c = (int)(i & 511);
        long e = i >> 9;
        float s  = esh[e * 4 + 0];
        float v0 = esh[e * 4 + 1], v1 = esh[e * 4 + 2], v2 = esh[e * 4 + 3];
        float m0 = g_MSG[0][e][c], m1 = g_MSG[1][e][c], m2 = g_MSG[2][e][c];
        float w0v = g_w[e][c], w1v = g_w[e][512 + c], w2v = g_w[e][1024 + c];
        g_psc[e][c] = w0v * (m0 * v0 + m1 * v1 + m2 * v2) * 0.5773502691896258f;
        float k2 = w2v * 0.7071067811865475f;
        float ws = w1v * s;
        g_PV[0][e][c] = ws * m0 + k2 * (m1 * v2 - m2 * v1);
        g_PV[1][e][c] = ws * m1 + k2 * (m2 * v0 - m0 * v2);
        g_PV[2][e][c] = ws * m2 + k2 * (m0 * v1 - m1 * v0);
    }
}

// ---------------- alpha post: LN + smooth_lrelu + head dot (1 warp / edge) ----------------
__global__ void k_alpha_post(const float* __restrict__ gg, const float* __restrict__ bb,
                             const float* __restrict__ adot)
{
    int gt = blockIdx.x * blockDim.x + threadIdx.x;
    int e = gt >> 5, lane = gt & 31;
    if (e >= C_E) return;
    float v0 = g_araw[e][lane * 2], v1 = g_araw[e][lane * 2 + 1];
    float s = v0 + v1, s2 = v0 * v0 + v1 * v1;
#pragma unroll
    for (int o = 16; o > 0; o >>= 1) {
        s  += __shfl_xor_sync(0xffffffffu, s, o);
        s2 += __shfl_xor_sync(0xffffffffu, s2, o);
    }
    float mu  = s * (1.f / 64.f);
    float var = s2 * (1.f / 64.f) - mu * mu;
    float inv = rsqrtf(var + C_EPS);
    float a0 = (v0 - mu) * inv * gg[lane * 2]     + bb[lane * 2];
    float a1 = (v1 - mu) * inv * gg[lane * 2 + 1] + bb[lane * 2 + 1];
    a0 = 0.6f * a0 + 0.4f * a0 * tanhf(0.5f * a0);
    a1 = 0.6f * a1 + 0.4f * a1 * tanhf(0.5f * a1);
    int h = lane >> 2;
    int m = (lane & 3) * 2;
    float p = a0 * adot[h * 8 + m] + a1 * adot[h * 8 + m + 1];
    p += __shfl_xor_sync(0xffffffffu, p, 1);
    p += __shfl_xor_sync(0xffffffffu, p, 2);
    if ((lane & 3) == 0) g_attr[e][h] = p;
}

// ---------------- softmax over K per (n,h) ----------------
__global__ void k_softmax()
{
    int i = blockIdx.x * blockDim.x + threadIdx.x;
    if (i >= C_N * C_H) return;
    int n = i >> 3, h = i & 7;
    float v[16]; float mx = -1e30f;
#pragma unroll
    for (int k = 0; k < 16; k++) { v[k] = g_attr[n * 16 + k][h]; mx = fmaxf(mx, v[k]); }
    float sum = 0.f;
#pragma unroll
    for (int k = 0; k < 16; k++) { v[k] = expf(v[k] - mx); sum += v[k]; }
    float is = 1.f / sum;
#pragma unroll
    for (int k = 0; k < 16; k++) g_att[n * 16 + k][h] = v[k] * is;
}

// ---------------- z = sum_k att * pv  (moves W_value after attention: 25.8GF -> 1.6GF) ----
__global__ void __launch_bounds__(256) k_z()
{
    int n = blockIdx.x, x = blockIdx.y;
    __shared__ float s_a[16][8];
    if (threadIdx.x < 128)
        s_a[threadIdx.x >> 3][threadIdx.x & 7] = g_att[n * 16 + (threadIdx.x >> 3)][threadIdx.x & 7];
    __syncthreads();
    for (int c = threadIdx.x; c < C_D; c += 256) {
        float acc[8] = {0, 0, 0, 0, 0, 0, 0, 0};
#pragma unroll
        for (int k = 0; k < 16; k++) {
            float pv = g_PV[x][n * 16 + k][c];
#pragma unroll
            for (int h = 0; h < 8; h++) acc[h] = fmaf(s_a[k][h], pv, acc[h]);
        }
#pragma unroll
        for (int h = 0; h < 8; h++) g_Z[x][n][h][c] = acc[h];
    }
}

// ---------------- vector-norm LayerNorm (vn_ln) ----------------
__global__ void __launch_bounds__(256) k_vnln(const float* __restrict__ Xin, float* __restrict__ Xout,
                                              const float* __restrict__ gg, const float* __restrict__ bb,
                                              int inter)
{
    int n = blockIdx.x, t = threadIdx.x;
    const long P = (long)C_N * C_D;
    __shared__ float rs[8], rs2[8];
    __shared__ float smu, sinv;
    float xv[2][3], nc[2];
    float s = 0.f, s2 = 0.f;
#pragma unroll
    for (int i = 0; i < 2; i++) {
        int c = t + i * 256;
#pragma unroll
        for (int xx = 0; xx < 3; xx++) xv[i][xx] = Xin[xx * P + (long)n * C_D + c];
        float v = sqrtf(xv[i][0] * xv[i][0] + xv[i][1] * xv[i][1] + xv[i][2] * xv[i][2] + C_EPS);
        nc[i] = v; s += v; s2 = fmaf(v, v, s2);
    }
#pragma unroll
    for (int o = 16; o > 0; o >>= 1) {
        s  += __shfl_xor_sync(0xffffffffu, s, o);
        s2 += __shfl_xor_sync(0xffffffffu, s2, o);
    }
    if ((t & 31) == 0) { rs[t >> 5] = s; rs2[t >> 5] = s2; }
    __syncthreads();
    if (t == 0) {
        float S = 0.f, S2 = 0.f;
        for (int i = 0; i < 8; i++) { S += rs[i]; S2 += rs2[i]; }
        float mu  = S * (1.f / 512.f);
        float var = S2 * (1.f / 512.f) - mu * mu;
        smu = mu; sinv = rsqrtf(var + C_EPS);
    }
    __syncthreads();
#pragma unroll
    for (int i = 0; i < 2; i++) {
        int c = t + i * 256;
        float ln = (nc[i] - smu) * sinv * gg[c] + bb[c];
        float sc = ln / nc[i];
        if (inter) {
#pragma unroll
            for (int xx = 0; xx < 3; xx++) Xout[(long)n * 1536 + c * 3 + xx] = xv[i][xx] * sc;
        } else {
#pragma unroll
            for (int xx = 0; xx < 3; xx++) Xout[xx * P + (long)n * C_D + c] = xv[i][xx] * sc;
        }
    }
}

// ---------------- FF gating (projection rejection) ----------------
__global__ void k_gate()
{
    const long P = (long)C_N * C_FF;
    const float* Y  = &g_Y[0][0][0];
    const float* Dv = &g_DV[0][0][0];
    float* O = &g_Y2[0][0][0];
    long stride = (long)gridDim.x * blockDim.x;
    for (long i = (long)blockIdx.x * blockDim.x + threadIdx.x; i < P; i += stride) {
        float y0 = Y[i], y1 = Y[P + i], y2 = Y[2 * P + i];
        float d0 = Dv[i], d1 = Dv[P + i], d2 = Dv[2 * P + i];
        float dot = y0 * d0 + y1 * d1 + y2 * d2;
        float dnn = d0 * d0 + d1 * d1 + d2 * d2 + C_EPS;
        float f = (dot >= 0.f) ? 0.f : 0.8f * dot / dnn;
        O[i]         = y0 - f * d0;
        O[P + i]     = y1 - f * d1;
        O[2 * P + i] = y2 - f * d2;
    }
}

// ---------------- host launch ----------------
extern "C" void kernel_launch(void* const* d_in, const int* in_sizes, int n_in,
                              void* d_out, int out_size)
{
    const float* tgt    = (const float*)d_in[0];
    const float* mem    = (const float*)d_in[1];
    const float* esh    = (const float*)d_in[2];
    const float* escal  = (const float*)d_in[3];
    const float* W_src  = (const float*)d_in[4];
    const float* W_dst  = (const float*)d_in[5];
    const float* fc_w1  = (const float*)d_in[6];
    const float* fc_b1  = (const float*)d_in[7];
    const float* fc_w2  = (const float*)d_in[8];
    const float* fc_b2  = (const float*)d_in[9];
    const float* fc_w3  = (const float*)d_in[10];
    const float* fc_b3  = (const float*)d_in[11];
    const float* W_alpha= (const float*)d_in[12];
    const float* ln_a_g = (const float*)d_in[13];
    const float* ln_a_b = (const float*)d_in[14];
    const float* adot   = (const float*)d_in[15];
    const float* W_value= (const float*)d_in[16];
    const float* W_proj = (const float*)d_in[17];
    const float* n1_g   = (const float*)d_in[18];
    const float* n1_b   = (const float*)d_in[19];
    const float* n2_g   = (const float*)d_in[20];
    const float* n2_b   = (const float*)d_in[21];
    const float* W_ff1  = (const float*)d_in[22];
    const float* W_ffd  = (const float*)d_in[23];
    const float* W_ff2  = (const float*)d_in[24];

    float *pT, *pM, *pTV, *pMSG, *ppsc, *pPV, *paraw, *pZ, *pOUT, *pXP, *pX1, *pY, *pDV, *pY2, *pY3, *pWaT;
    cudaGetSymbolAddress((void**)&pT,   g_T);
    cudaGetSymbolAddress((void**)&pM,   g_M);
    cudaGetSymbolAddress((void**)&pTV,  g_TV);
    cudaGetSymbolAddress((void**)&pMSG, g_MSG);
    cudaGetSymbolAddress((void**)&ppsc, g_psc);
    cudaGetSymbolAddress((void**)&pPV,  g_PV);
    cudaGetSymbolAddress((void**)&paraw,g_araw);
    cudaGetSymbolAddress((void**)&pZ,   g_Z);
    cudaGetSymbolAddress((void**)&pOUT, g_OUT);
    cudaGetSymbolAddress((void**)&pXP,  g_XP);
    cudaGetSymbolAddress((void**)&pX1,  g_X1);
    cudaGetSymbolAddress((void**)&pY,   g_Y);
    cudaGetSymbolAddress((void**)&pDV,  g_DV);
    cudaGetSymbolAddress((void**)&pY2,  g_Y2);
    cudaGetSymbolAddress((void**)&pY3,  g_Y3);
    cudaGetSymbolAddress((void**)&pWaT, g_WaT);

    const long NP_D  = (long)C_N * C_D;      // 524288
    const long EP_D  = (long)C_E * C_D;      // 8388608
    const long NP_FF = (long)C_N * C_FF;     // 2097152
    const long NHD   = (long)C_N * C_H * C_D;

    // 1) transposes
    k_transpose_in<<<4096, 256>>>(tgt, mem);
    k_transpose_wa<<<128, 256>>>(W_alpha);

    // 2) tv = W_dst @ tgt
    gemm_nt<128,128,8,8><<<dim3(4,8,3), 256>>>(pT, W_dst, pTV, nullptr,
        C_N, C_D, C_D, C_D, C_D, C_D, NP_D,0, 0,0, NP_D,0, 1, 1,0, 0);

    // 3) msg = W_src @ memory + tv[e/K]
    gemm_nt<128,128,8,8><<<dim3(4,128,3), 256>>>(pM, W_src, pMSG, pTV,
        C_E, C_D, C_D, C_D, C_D, C_D, EP_D,0, 0,0, EP_D,0, 1, C_K, C_D, NP_D);

    // 4) edge MLP -> g_w
    k_mlp<<<C_E/64, 256>>>(escal, fc_w1, fc_b1, fc_w2, fc_b2, fc_w3, fc_b3);

    // 5) p_sc / pv
    k_pointwise<<<2048, 256>>>(esh);

    // 6) a_raw = p_sc @ W_alpha
    gemm_nt<64,64,4,4><<<dim3(1,256,1), 256>>>(ppsc, pWaT, paraw, nullptr,
        C_E, C_MA, C_D, C_D, C_D, C_MA, 0,0, 0,0, 0,0, 1, 1,0, 0);

    // 7) LN + lrelu + head dot, then softmax over K
    k_alpha_post<<<2048, 256>>>(ln_a_g, ln_a_b, adot);
    k_softmax<<<32, 256>>>();

    // 8) z = sum_k att * pv
    k_z<<<dim3(C_N, 3), 256>>>();

    // 9) out = W_value @ z (per head), then proj + tv
    gemm_nt<64,64,4,4><<<dim3(1,16,24), 256>>>(pZ, W_value, pOUT, nullptr,
        C_N, 64, C_D, C_H*C_D, C_D, C_D, NHD, C_D, 0, 64*C_D, NP_D, 64, C_H, 1,0, 0);
    gemm_nt<128,128,8,8><<<dim3(4,8,3), 256>>>(pOUT, W_proj, pXP, pTV,
        C_N, C_D, C_D, C_D, C_D, C_D, NP_D,0, 0,0, NP_D,0, 1, 1, C_D, NP_D);

    // 10) vn_ln #1
    k_vnln<<<C_N, 256>>>(pXP, pX1, n1_g, n1_b, 0);

    // 11) FF block
    gemm_nt<128,128,8,8><<<dim3(16,8,3), 256>>>(pX1, W_ff1, pY, nullptr,
        C_N, C_FF, C_D, C_D, C_D, C_FF, NP_D,0, 0,0, NP_FF,0, 1, 1,0, 0);
    gemm_nt<128,128,8,8><<<dim3(16,8,3), 256>>>(pY, W_ffd, pDV, nullptr,
        C_N, C_FF, C_FF, C_FF, C_FF, C_FF, NP_FF,0, 0,0, NP_FF,0, 1, 1,0, 0);
    k_gate<<<2048, 256>>>();
    gemm_nt<128,128,8,8><<<dim3(4,8,3), 256>>>(pY2, W_ff2, pY3, pX1,
        C_N, C_D, C_FF, C_FF, C_FF, C_D, NP_FF,0, 0,0, NP_D,0, 1, 1, C_D, NP_D);

    // 12) vn_ln #2 -> interleaved (n, c*3+x) output
    k_vnln<<<C_N, 256>>>(pY3, (float*)d_out, n2_g, n2_b, 1);
}

// round 3
// speedup vs baseline: 2.3363x; 2.3363x over previous
#include <cuda_runtime.h>
#include <cuda_bf16.h>
#include <math.h>
#include <stdint.h>

// ---------------- problem constants ----------------
#define C_N   1024
#define C_K   16
#define C_D   512
#define C_H   8
#define C_FF  2048
#define C_MA  64
#define C_ES  64
#define C_E   (C_N * C_K)      // 16384
#define C_EPS 1e-6f

// ---------------- scratch (device globals; no allocation) ----------------
__device__ float g_T   [3][C_N][C_D];
__device__ float g_M   [3][C_E][C_D];
__device__ float g_TV  [3][C_N][C_D];
__device__ float g_MSG [3][C_E][C_D];
__device__ float g_w   [C_E][3*C_D];
__device__ float g_psc [C_E][C_D];
__device__ float g_PV  [3][C_E][C_D];
__device__ float g_araw[C_E][C_MA];
__device__ float g_attr[C_E][C_H];
__device__ float g_att [C_E][C_H];
__device__ float g_Z   [3][C_N][C_H][C_D];
__device__ float g_OUT [3][C_N][C_D];
__device__ float g_XP  [3][C_N][C_D];
__device__ float g_X1  [3][C_N][C_D];
__device__ float g_Y   [3][C_N][C_FF];
__device__ float g_DV  [3][C_N][C_FF];
__device__ float g_Y2  [3][C_N][C_FF];
__device__ float g_Y3  [3][C_N][C_D];
__device__ float g_WaT [C_MA][C_D];

// ================= mma.sync bf16 helpers =================
__device__ __forceinline__ void mma_bf16(float* c, const uint32_t* a, const uint32_t* b) {
    asm volatile("mma.sync.aligned.m16n8k16.row.col.f32.bf16.bf16.f32 "
                 "{%0,%1,%2,%3},{%4,%5,%6,%7},{%8,%9},{%0,%1,%2,%3};"
                 : "+f"(c[0]), "+f"(c[1]), "+f"(c[2]), "+f"(c[3])
                 : "r"(a[0]), "r"(a[1]), "r"(a[2]), "r"(a[3]), "r"(b[0]), "r"(b[1]));
}

// split fp32x4 -> bf16 hi quad + bf16 lo quad, store to shared
__device__ __forceinline__ void cvt_store(char* hip, char* lop, float4 v) {
    __nv_bfloat16 bx = __float2bfloat16_rn(v.x);
    __nv_bfloat16 by = __float2bfloat16_rn(v.y);
    __nv_bfloat16 bz = __float2bfloat16_rn(v.z);
    __nv_bfloat16 bw = __float2bfloat16_rn(v.w);
    __nv_bfloat162 h01(bx, by), h23(bz, bw);
    *(uint2*)hip = make_uint2(*(uint32_t*)&h01, *(uint32_t*)&h23);
    __nv_bfloat16 lx = __float2bfloat16_rn(v.x - __bfloat162float(bx));
    __nv_bfloat16 ly = __float2bfloat16_rn(v.y - __bfloat162float(by));
    __nv_bfloat16 lz = __float2bfloat16_rn(v.z - __bfloat162float(bz));
    __nv_bfloat16 lw = __float2bfloat16_rn(v.w - __bfloat162float(bw));
    __nv_bfloat162 l01(lx, ly), l23(lz, lw);
    *(uint2*)lop = make_uint2(*(uint32_t*)&l01, *(uint32_t*)&l23);
}

// ============ tensor-core NT GEMM: C[m,n] = sum_k A[m,k]*B[n,k] (+Add) ============
// fp32-class accuracy via bf16 hi/lo split (3 HMMA passes). M%128==0, N%BN==0, K%32==0.
template<int BN>
__global__ void __launch_bounds__(256, BN == 64 ? 2 : 1) gemm_mma(
    const float* __restrict__ A, const float* __restrict__ B,
    float* __restrict__ C, const float* __restrict__ Add,
    int lda, int ldb, int ldc, int Kc,
    long sA1, long sA2, long sB1, long sB2, long sC1, long sC2, int nz2,
    int addDiv, int ldadd, long sAdd1)
{
    constexpr int WN   = BN / 4;       // warp n-tile
    constexpr int NSUB = BN / 32;      // 8-wide n subtiles per warp
    constexpr int NBF4 = BN / 32;      // B float4 loads per thread per chunk
    constexpr int ABY  = 128 * 80;     // bytes of one A tile (128 rows x 40 bf16)
    constexpr int BBY  = BN * 80;
    constexpr int STG  = 2 * ABY + 2 * BBY;

    extern __shared__ __align__(16) char sm[];
    const int t = threadIdx.x, wid = t >> 5, lane = t & 31;
    const int g = lane >> 2, tq = lane & 3;
    const int wm = wid & 1, wn = wid >> 1;

    const int z = blockIdx.z, z1 = z / nz2, z2 = z - z1 * nz2;
    const long m0 = (long)blockIdx.y * 128, n0 = (long)blockIdx.x * BN;
    const float* Ag = A + z1 * sA1 + z2 * sA2 + m0 * lda;
    const float* Bg = B + z1 * sB1 + z2 * sB2 + n0 * ldb;

    float acc[4][NSUB][4];
#pragma unroll
    for (int mi = 0; mi < 4; mi++)
#pragma unroll
        for (int ni = 0; ni < NSUB; ni++)
#pragma unroll
            for (int j = 0; j < 4; j++) acc[mi][ni][j] = 0.f;

    const int nch = Kc >> 5;
    float4 pa[4], pb[NBF4];

    // ---- prologue: load + convert + store chunk 0 ----
#pragma unroll
    for (int i = 0; i < 4; i++) {
        int idx = t + i * 256;
        pa[i] = *(const float4*)(Ag + (long)(idx >> 3) * lda + (idx & 7) * 4);
    }
#pragma unroll
    for (int i = 0; i < NBF4; i++) {
        int idx = t + i * 256;
        pb[i] = *(const float4*)(Bg + (long)(idx >> 3) * ldb + (idx & 7) * 4);
    }
#pragma unroll
    for (int i = 0; i < 4; i++) {
        int idx = t + i * 256, off = (idx >> 3) * 80 + (idx & 7) * 8;
        cvt_store(sm + off, sm + ABY + off, pa[i]);
    }
#pragma unroll
    for (int i = 0; i < NBF4; i++) {
        int idx = t + i * 256, off = (idx >> 3) * 80 + (idx & 7) * 8;
        cvt_store(sm + 2 * ABY + off, sm + 2 * ABY + BBY + off, pb[i]);
    }
    __syncthreads();

    const int aoff = (wm * 64 + g) * 80 + tq * 4;
    const int boff = (wn * WN + g) * 80 + tq * 4;

    for (int ch = 0; ch < nch; ch++) {
        const bool more = (ch + 1) < nch;
        if (more) {
            const float* Ap = Ag + (ch + 1) * 32;
#pragma unroll
            for (int i = 0; i < 4; i++) {
                int idx = t + i * 256;
                pa[i] = *(const float4*)(Ap + (long)(idx >> 3) * lda + (idx & 7) * 4);
            }
            const float* Bp = Bg + (ch + 1) * 32;
#pragma unroll
            for (int i = 0; i < NBF4; i++) {
                int idx = t + i * 256;
                pb[i] = *(const float4*)(Bp + (long)(idx >> 3) * ldb + (idx & 7) * 4);
            }
        }
        // ---- MMA on stage ch&1 ----
        const char* sA = sm + (ch & 1) * STG;
        const char* sB = sA + 2 * ABY;
#pragma unroll
        for (int ks = 0; ks < 2; ks++) {
            const int ko = ks * 32;
            uint32_t fa[16], fbh[2 * NSUB], fbl[2 * NSUB];
#pragma unroll
            for (int mi = 0; mi < 4; mi++) {
                const char* p = sA + aoff + ko + mi * 1280;
                fa[mi * 4 + 0] = *(const uint32_t*)(p);
                fa[mi * 4 + 1] = *(const uint32_t*)(p + 640);
                fa[mi * 4 + 2] = *(const uint32_t*)(p + 16);
                fa[mi * 4 + 3] = *(const uint32_t*)(p + 656);
            }
#pragma unroll
            for (int ni = 0; ni < NSUB; ni++) {
                const char* p = sB + boff + ko + ni * 640;
                fbh[ni * 2] = *(const uint32_t*)p;
                fbh[ni * 2 + 1] = *(const uint32_t*)(p + 16);
            }
#pragma unroll
            for (int mi = 0; mi < 4; mi++)
#pragma unroll
                for (int ni = 0; ni < NSUB; ni++)
                    mma_bf16(acc[mi][ni], &fa[mi * 4], &fbh[ni * 2]);   // hi*hi
#pragma unroll
            for (int ni = 0; ni < NSUB; ni++) {
                const char* p = sB + BBY + boff + ko + ni * 640;
                fbl[ni * 2] = *(const uint32_t*)p;
                fbl[ni * 2 + 1] = *(const uint32_t*)(p + 16);
            }
#pragma unroll
            for (int mi = 0; mi < 4; mi++)
#pragma unroll
                for (int ni = 0; ni < NSUB; ni++)
                    mma_bf16(acc[mi][ni], &fa[mi * 4], &fbl[ni * 2]);   // hi*lo
#pragma unroll
            for (int mi = 0; mi < 4; mi++) {
                const char* p = sA + ABY + aoff + ko + mi * 1280;
                fa[mi * 4 + 0] = *(const uint32_t*)(p);
                fa[mi * 4 + 1] = *(const uint32_t*)(p + 640);
                fa[mi * 4 + 2] = *(const uint32_t*)(p + 16);
                fa[mi * 4 + 3] = *(const uint32_t*)(p + 656);
            }
#pragma unroll
            for (int mi = 0; mi < 4; mi++)
#pragma unroll
                for (int ni = 0; ni < NSUB; ni++)
                    mma_bf16(acc[mi][ni], &fa[mi * 4], &fbh[ni * 2]);   // lo*hi
        }
        if (more) {
            char* s1 = sm + ((ch + 1) & 1) * STG;
#pragma unroll
            for (int i = 0; i < 4; i++) {
                int idx = t + i * 256, off = (idx >> 3) * 80 + (idx & 7) * 8;
                cvt_store(s1 + off, s1 + ABY + off, pa[i]);
            }
#pragma unroll
            for (int i = 0; i < NBF4; i++) {
                int idx = t + i * 256, off = (idx >> 3) * 80 + (idx & 7) * 8;
                cvt_store(s1 + 2 * ABY + off, s1 + 2 * ABY + BBY + off, pb[i]);
            }
        }
        __syncthreads();
    }

    // ---- epilogue ----
    float* Cp = C + z1 * sC1 + z2 * sC2;
    const float* Ad = Add ? (Add + z1 * sAdd1) : (const float*)0;
#pragma unroll
    for (int mi = 0; mi < 4; mi++) {
        long r0 = m0 + wm * 64 + mi * 16 + g;
#pragma unroll
        for (int ni = 0; ni < NSUB; ni++) {
            long col = n0 + wn * WN + ni * 8 + tq * 2;
            float2 v0 = make_float2(acc[mi][ni][0], acc[mi][ni][1]);
            float2 v1 = make_float2(acc[mi][ni][2], acc[mi][ni][3]);
            if (Ad) {
                float2 a0 = *(const float2*)(Ad + (r0 / addDiv) * (long)ldadd + col);
                float2 a1 = *(const float2*)(Ad + ((r0 + 8) / addDiv) * (long)ldadd + col);
                v0.x += a0.x; v0.y += a0.y; v1.x += a1.x; v1.y += a1.y;
            }
            *(float2*)(Cp + r0 * ldc + col) = v0;
            *(float2*)(Cp + (r0 + 8) * ldc + col) = v1;
        }
    }
}

// ---------------- transposes ----------------
__global__ void k_transpose_in(const float* __restrict__ tgt, const float* __restrict__ mem)
{
    long stride = (long)gridDim.x * blockDim.x;
    long base   = (long)blockIdx.x * blockDim.x + threadIdx.x;
    const long TT = (long)C_N * C_D * 3;
    for (long i = base; i < TT; i += stride) {
        int  x  = (int)(i % 3);
        long nc = i / 3;
        g_T[x][nc >> 9][nc & 511] = tgt[i];
    }
    const long TMm = (long)C_E * C_D * 3;
    for (long i = base; i < TMm; i += stride) {
        int  x  = (int)(i % 3);
        long ec = i / 3;
        g_M[x][ec >> 9][ec & 511] = mem[i];
    }
}

__global__ void k_transpose_wa(const float* __restrict__ wa)
{
    int i = blockIdx.x * blockDim.x + threadIdx.x;
    if (i < C_D * C_MA) g_WaT[i & 63][i >> 6] = wa[i];
}

// ---------------- fused edge MLP ----------------
__global__ void __launch_bounds__(256) k_mlp(
    const float* __restrict__ es, const float* __restrict__ w1, const float* __restrict__ b1,
    const float* __restrict__ w2, const float* __restrict__ b2,
    const float* __restrict__ w3, const float* __restrict__ b3)
{
    __shared__ float s_es[64][65];
    __shared__ float s_w1[64][32];
    __shared__ float s_w2[32][32];
    __shared__ float s_h1[64][33];
    __shared__ float s_h2[64][33];
    const int t = threadIdx.x;
    const long e0 = (long)blockIdx.x * 64;

    for (int i = t; i < 64 * 32; i += 256) s_w1[i >> 5][i & 31] = w1[i];
    for (int i = t; i < 32 * 32; i += 256) s_w2[i >> 5][i & 31] = w2[i];
    for (int i = t; i < 64 * 64; i += 256) s_es[i >> 6][i & 63] = es[e0 * 64 + i];
    __syncthreads();

    for (int i = t; i < 64 * 32; i += 256) {
        int e = i >> 5, j = i & 31;
        float acc = b1[j];
#pragma unroll 8
        for (int c = 0; c < 64; c++) acc = fmaf(s_es[e][c], s_w1[c][j], acc);
        s_h1[e][j] = acc / (1.f + expf(-acc));
    }
    __syncthreads();
    for (int i = t; i < 64 * 32; i += 256) {
        int e = i >> 5, j = i & 31;
        float acc = b2[j];
#pragma unroll 8
        for (int c = 0; c < 32; c++) acc = fmaf(s_h1[e][c], s_w2[c][j], acc);
        s_h2[e][j] = acc / (1.f + expf(-acc));
    }
    __syncthreads();
    for (int i = t; i < 64 * 1536; i += 256) {
        int e = i / 1536, o = i - e * 1536;
        float acc = b3[o];
#pragma unroll 8
        for (int c = 0; c < 32; c++) acc = fmaf(s_h2[e][c], w3[c * 1536 + o], acc);
        g_w[e0 + e][o] = acc;
    }
}

// ---------------- pointwise equivariant products ----------------
__global__ void k_pointwise(const float* __restrict__ esh)
{
    long stride = (long)gridDim.x * blockDim.x;
    for (long i = (long)blockIdx.x * blockDim.x + threadIdx.x; i < (long)C_E * C_D; i += stride) {
        int  c = (int)(i & 511);
        long e = i >> 9;
        float s  = esh[e * 4 + 0];
        float v0 = esh[e * 4 + 1], v1 = esh[e * 4 + 2], v2 = esh[e * 4 + 3];
        float m0 = g_MSG[0][e][c], m1 = g_MSG[1][e][c], m2 = g_MSG[2][e][c];
        float w0v = g_w[e][c], w1v = g_w[e][512 + c], w2v = g_w[e][1024 + c];
        g_psc[e][c] = w0v * (m0 * v0 + m1 * v1 + m2 * v2) * 0.5773502691896258f;
        float k2 = w2v * 0.7071067811865475f;
        float ws = w1v * s;
        g_PV[0][e][c] = ws * m0 + k2 * (m1 * v2 - m2 * v1);
        g_PV[1][e][c] = ws * m1 + k2 * (m2 * v0 - m0 * v2);
        g_PV[2][e][c] = ws * m2 + k2 * (m0 * v1 - m1 * v0);
    }
}

// ---------------- alpha post: LN + smooth_lrelu + head dot ----------------
__global__ void k_alpha_post(const float* __restrict__ gg, const float* __restrict__ bb,
                             const float* __restrict__ adot)
{
    int gt = blockIdx.x * blockDim.x + threadIdx.x;
    int e = gt >> 5, lane = gt & 31;
    if (e >= C_E) return;
    float v0 = g_araw[e][lane * 2], v1 = g_araw[e][lane * 2 + 1];
    float s = v0 + v1, s2 = v0 * v0 + v1 * v1;
#pragma unroll
    for (int o = 16; o > 0; o >>= 1) {
        s  += __shfl_xor_sync(0xffffffffu, s, o);
        s2 += __shfl_xor_sync(0xffffffffu, s2, o);
    }
    float mu  = s * (1.f / 64.f);
    float var = s2 * (1.f / 64.f) - mu * mu;
    float inv = rsqrtf(var + C_EPS);
    float a0 = (v0 - mu) * inv * gg[lane * 2]     + bb[lane * 2];
    float a1 = (v1 - mu) * inv * gg[lane * 2 + 1] + bb[lane * 2 + 1];
    a0 = 0.6f * a0 + 0.4f * a0 * tanhf(0.5f * a0);
    a1 = 0.6f * a1 + 0.4f * a1 * tanhf(0.5f * a1);
    int h = lane >> 2;
    int m = (lane & 3) * 2;
    float p = a0 * adot[h * 8 + m] + a1 * adot[h * 8 + m + 1];
    p += __shfl_xor_sync(0xffffffffu, p, 1);
    p += __shfl_xor_sync(0xffffffffu, p, 2);
    if ((lane & 3) == 0) g_attr[e][h] = p;
}

// ---------------- softmax over K per (n,h) ----------------
__global__ void k_softmax()
{
    int i = blockIdx.x * blockDim.x + threadIdx.x;
    if (i >= C_N * C_H) return;
    int n = i >> 3, h = i & 7;
    float v[16]; float mx = -1e30f;
#pragma unroll
    for (int k = 0; k < 16; k++) { v[k] = g_attr[n * 16 + k][h]; mx = fmaxf(mx, v[k]); }
    float sum = 0.f;
#pragma unroll
    for (int k = 0; k < 16; k++) { v[k] = expf(v[k] - mx); sum += v[k]; }
    float is = 1.f / sum;
#pragma unroll
    for (int k = 0; k < 16; k++) g_att[n * 16 + k][h] = v[k] * is;
}

// ---------------- z = sum_k att * pv ----------------
__global__ void __launch_bounds__(256) k_z()
{
    int n = blockIdx.x, x = blockIdx.y;
    __shared__ float s_a[16][8];
    if (threadIdx.x < 128)
        s_a[threadIdx.x >> 3][threadIdx.x & 7] = g_att[n * 16 + (threadIdx.x >> 3)][threadIdx.x & 7];
    __syncthreads();
    for (int c = threadIdx.x; c < C_D; c += 256) {
        float acc[8] = {0, 0, 0, 0, 0, 0, 0, 0};
#pragma unroll
        for (int k = 0; k < 16; k++) {
            float pv = g_PV[x][n * 16 + k][c];
#pragma unroll
            for (int h = 0; h < 8; h++) acc[h] = fmaf(s_a[k][h], pv, acc[h]);
        }
#pragma unroll
        for (int h = 0; h < 8; h++) g_Z[x][n][h][c] = acc[h];
    }
}

// ---------------- vector-norm LayerNorm (vn_ln) ----------------
__global__ void __launch_bounds__(256) k_vnln(const float* __restrict__ Xin, float* __restrict__ Xout,
                                              const float* __restrict__ gg, const float* __restrict__ bb,
                                              int inter)
{
    int n = blockIdx.x, t = threadIdx.x;
    const long P = (long)C_N * C_D;
    __shared__ float rs[8], rs2[8];
    __shared__ float smu, sinv;
    float xv[2][3], nc[2];
    float s = 0.f, s2 = 0.f;
#pragma unroll
    for (int i = 0; i < 2; i++) {
        int c = t + i * 256;
#pragma unroll
        for (int xx = 0; xx < 3; xx++) xv[i][xx] = Xin[xx * P + (long)n * C_D + c];
        float v = sqrtf(xv[i][0] * xv[i][0] + xv[i][1] * xv[i][1] + xv[i][2] * xv[i][2] + C_EPS);
        nc[i] = v; s += v; s2 = fmaf(v, v, s2);
    }
#pragma unroll
    for (int o = 16; o > 0; o >>= 1) {
        s  += __shfl_xor_sync(0xffffffffu, s, o);
        s2 += __shfl_xor_sync(0xffffffffu, s2, o);
    }
    if ((t & 31) == 0) { rs[t >> 5] = s; rs2[t >> 5] = s2; }
    __syncthreads();
    if (t == 0) {
        float S = 0.f, S2 = 0.f;
        for (int i = 0; i < 8; i++) { S += rs[i]; S2 += rs2[i]; }
        float mu  = S * (1.f / 512.f);
        float var = S2 * (1.f / 512.f) - mu * mu;
        smu = mu; sinv = rsqrtf(var + C_EPS);
    }
    __syncthreads();
#pragma unroll
    for (int i = 0; i < 2; i++) {
        int c = t + i * 256;
        float ln = (nc[i] - smu) * sinv * gg[c] + bb[c];
        float sc = ln / nc[i];
        if (inter) {
#pragma unroll
            for (int xx = 0; xx < 3; xx++) Xout[(long)n * 1536 + c * 3 + xx] = xv[i][xx] * sc;
        } else {
#pragma unroll
            for (int xx = 0; xx < 3; xx++) Xout[xx * P + (long)n * C_D + c] = xv[i][xx] * sc;
        }
    }
}

// ---------------- FF gating (projection rejection) ----------------
__global__ void k_gate()
{
    const long P = (long)C_N * C_FF;
    const float* Y  = &g_Y[0][0][0];
    const float* Dv = &g_DV[0][0][0];
    float* O = &g_Y2[0][0][0];
    long stride = (long)gridDim.x * blockDim.x;
    for (long i = (long)blockIdx.x * blockDim.x + threadIdx.x; i < P; i += stride) {
        float y0 = Y[i], y1 = Y[P + i], y2 = Y[2 * P + i];
        float d0 = Dv[i], d1 = Dv[P + i], d2 = Dv[2 * P + i];
        float dot = y0 * d0 + y1 * d1 + y2 * d2;
        float dnn = d0 * d0 + d1 * d1 + d2 * d2 + C_EPS;
        float f = (dot >= 0.f) ? 0.f : 0.8f * dot / dnn;
        O[i]         = y0 - f * d0;
        O[P + i]     = y1 - f * d1;
        O[2 * P + i] = y2 - f * d2;
    }
}

// ---------------- host launch ----------------
extern "C" void kernel_launch(void* const* d_in, const int* in_sizes, int n_in,
                              void* d_out, int out_size)
{
    const float* tgt    = (const float*)d_in[0];
    const float* mem    = (const float*)d_in[1];
    const float* esh    = (const float*)d_in[2];
    const float* escal  = (const float*)d_in[3];
    const float* W_src  = (const float*)d_in[4];
    const float* W_dst  = (const float*)d_in[5];
    const float* fc_w1  = (const float*)d_in[6];
    const float* fc_b1  = (const float*)d_in[7];
    const float* fc_w2  = (const float*)d_in[8];
    const float* fc_b2  = (const float*)d_in[9];
    const float* fc_w3  = (const float*)d_in[10];
    const float* fc_b3  = (const float*)d_in[11];
    const float* W_alpha= (const float*)d_in[12];
    const float* ln_a_g = (const float*)d_in[13];
    const float* ln_a_b = (const float*)d_in[14];
    const float* adot   = (const float*)d_in[15];
    const float* W_value= (const float*)d_in[16];
    const float* W_proj = (const float*)d_in[17];
    const float* n1_g   = (const float*)d_in[18];
    const float* n1_b   = (const float*)d_in[19];
    const float* n2_g   = (const float*)d_in[20];
    const float* n2_b   = (const float*)d_in[21];
    const float* W_ff1  = (const float*)d_in[22];
    const float* W_ffd  = (const float*)d_in[23];
    const float* W_ff2  = (const float*)d_in[24];

    float *pT, *pM, *pTV, *pMSG, *ppsc, *pPV, *paraw, *pZ, *pOUT, *pXP, *pX1, *pY, *pDV, *pY2, *pY3, *pWaT;
    cudaGetSymbolAddress((void**)&pT,   g_T);
    cudaGetSymbolAddress((void**)&pM,   g_M);
    cudaGetSymbolAddress((void**)&pTV,  g_TV);
    cudaGetSymbolAddress((void**)&pMSG, g_MSG);
    cudaGetSymbolAddress((void**)&ppsc, g_psc);
    cudaGetSymbolAddress((void**)&pPV,  g_PV);
    cudaGetSymbolAddress((void**)&paraw,g_araw);
    cudaGetSymbolAddress((void**)&pZ,   g_Z);
    cudaGetSymbolAddress((void**)&pOUT, g_OUT);
    cudaGetSymbolAddress((void**)&pXP,  g_XP);
    cudaGetSymbolAddress((void**)&pX1,  g_X1);
    cudaGetSymbolAddress((void**)&pY,   g_Y);
    cudaGetSymbolAddress((void**)&pDV,  g_DV);
    cudaGetSymbolAddress((void**)&pY2,  g_Y2);
    cudaGetSymbolAddress((void**)&pY3,  g_Y3);
    cudaGetSymbolAddress((void**)&pWaT, g_WaT);

    const long NP_D  = (long)C_N * C_D;
    const long EP_D  = (long)C_E * C_D;
    const long NP_FF = (long)C_N * C_FF;
    const long NHD   = (long)C_N * C_H * C_D;

    // dynamic smem: 2 stages * (2*A + 2*B) tiles, 80B row stride
    const int SM128 = 2 * (2 * 128 * 80 + 2 * 128 * 80);  // 81920
    const int SM64  = 2 * (2 * 128 * 80 + 2 * 64 * 80);   // 61440
    cudaFuncSetAttribute(gemm_mma<128>, cudaFuncAttributeMaxDynamicSharedMemorySize, SM128);
    cudaFuncSetAttribute(gemm_mma<64>,  cudaFuncAttributeMaxDynamicSharedMemorySize, SM64);

    // 1) transposes
    k_transpose_in<<<4096, 256>>>(tgt, mem);
    k_transpose_wa<<<128, 256>>>(W_alpha);

    // 2) tv = W_dst @ tgt
    gemm_mma<128><<<dim3(4, 8, 3), 256, SM128>>>(pT, W_dst, pTV, nullptr,
        C_D, C_D, C_D, C_D, NP_D, 0, 0, 0, NP_D, 0, 1, 1, 0, 0);

    // 3) msg = W_src @ memory + tv[e/K]
    gemm_mma<128><<<dim3(4, 128, 3), 256, SM128>>>(pM, W_src, pMSG, pTV,
        C_D, C_D, C_D, C_D, EP_D, 0, 0, 0, EP_D, 0, 1, C_K, C_D, NP_D);

    // 4) edge MLP -> g_w
    k_mlp<<<C_E / 64, 256>>>(escal, fc_w1, fc_b1, fc_w2, fc_b2, fc_w3, fc_b3);

    // 5) p_sc / pv
    k_pointwise<<<2048, 256>>>(esh);

    // 6) a_raw = p_sc @ W_alpha
    gemm_mma<64><<<dim3(1, 128, 1), 256, SM64>>>(ppsc, pWaT, paraw, nullptr,
        C_D, C_D, C_MA, C_D, 0, 0, 0, 0, 0, 0, 1, 1, 0, 0);

    // 7) LN + lrelu + head dot, then softmax over K
    k_alpha_post<<<2048, 256>>>(ln_a_g, ln_a_b, adot);
    k_softmax<<<32, 256>>>();

    // 8) z = sum_k att * pv
    k_z<<<dim3(C_N, 3), 256>>>();

    // 9) out = W_value @ z (per head), then proj + tv
    gemm_mma<64><<<dim3(1, 8, 24), 256, SM64>>>(pZ, W_value, pOUT, nullptr,
        C_H * C_D, C_D, C_D, C_D, NHD, C_D, 0, 64 * C_D, NP_D, 64, C_H, 1, 0, 0);
    gemm_mma<128><<<dim3(4, 8, 3), 256, SM128>>>(pOUT, W_proj, pXP, pTV,
        C_D, C_D, C_D, C_D, NP_D, 0, 0, 0, NP_D, 0, 1, 1, C_D, NP_D);

    // 10) vn_ln #1
    k_vnln<<<C_N, 256>>>(pXP, pX1, n1_g, n1_b, 0);

    // 11) FF block
    gemm_mma<128><<<dim3(16, 8, 3), 256, SM128>>>(pX1, W_ff1, pY, nullptr,
        C_D, C_D, C_FF, C_D, NP_D, 0, 0, 0, NP_FF, 0, 1, 1, 0, 0);
    gemm_mma<128><<<dim3(16, 8, 3), 256, SM128>>>(pY, W_ffd, pDV, nullptr,
        C_FF, C_FF, C_FF, C_FF, NP_FF, 0, 0, 0, NP_FF, 0, 1, 1, 0, 0);
    k_gate<<<2048, 256>>>();
    gemm_mma<128><<<dim3(4, 8, 3), 256, SM128>>>(pY2, W_ff2, pY3, pX1,
        C_FF, C_FF, C_D, C_FF, NP_FF, 0, 0, 0, NP_D, 0, 1, 1, C_D, NP_D);

    // 12) vn_ln #2 -> interleaved (n, c*3+x) output
    k_vnln<<<C_N, 256>>>(pY3, (float*)d_out, n2_g, n2_b, 1);
}